// round 15
// baseline (speedup 1.0000x reference)
#include <cuda_runtime.h>
#include <cstdint>

#define N_NODES 100000
#define D 64
#define CAP 64            // per-node in-edge bucket capacity (Poisson(16), max ~45)
#define OVF_CAP 8192      // overflow edge list (statistically never used)

// Scratch (__device__ globals: allocation-free per harness rules)
__device__ int   g_is64;                          // edge_index dtype flag
__device__ float g_deg[N_NODES];                  // raw weighted out-degree
__device__ int   g_cnt[N_NODES];                  // bucket fill counters
__device__ int2  g_bucket[(size_t)N_NODES * CAP]; // {row, bitcast(w)}
__device__ int   g_ovf_cnt;
__device__ int   g_ovf[OVF_CAP];                  // overflow edge ids
__device__ __align__(16) float g_y[(size_t)N_NODES * D];   // y = x @ W1

__device__ __forceinline__ float dinv_of(float d) {
    return (d > 0.f) ? rsqrtf(d) : 0.f;
}

__device__ __forceinline__ void load_edge(const void* ei, int E, int e,
                                          int& r, int& c) {
    if (g_is64) {
        const long long* p = (const long long*)ei;
        r = (int)p[e];
        c = (int)p[(size_t)E + e];
    } else {
        const int* p = (const int*)ei;
        r = p[e];
        c = p[E + e];
    }
}

// ---------------------------------------------------------------------------
// K1: zero deg + counters; block 0 also detects edge_index dtype.
// ---------------------------------------------------------------------------
__global__ void zero_detect_kernel(const int* __restrict__ ei) {
    int i = blockIdx.x * blockDim.x + threadIdx.x;
    if (i < N_NODES) { g_deg[i] = 0.f; g_cnt[i] = 0; }
    if (i == 0) g_ovf_cnt = 0;
    if (blockIdx.x == 0) {
        __shared__ int any;
        if (threadIdx.x == 0) any = 0;
        __syncthreads();
        int loc = 0;
        for (int k = 1 + 2 * threadIdx.x; k < 4096; k += 2 * blockDim.x)
            loc |= ei[k];
        if (loc) atomicOr(&any, 1);
        __syncthreads();
        if (threadIdx.x == 0) g_is64 = any ? 0 : 1;
    }
}

// ---------------------------------------------------------------------------
// K2: single edge pass — deg[row] += w AND append {row, w} to col's bucket.
// ---------------------------------------------------------------------------
__global__ void edge_pass_kernel(const void* __restrict__ ei,
                                 const float* __restrict__ ew, int E) {
    int e = blockIdx.x * blockDim.x + threadIdx.x;
    if (e >= E) return;
    int r, c;
    load_edge(ei, E, e, r, c);
    float w = __ldg(&ew[e]);
    atomicAdd(&g_deg[r], w);
    int pos = atomicAdd(&g_cnt[c], 1);
    if (pos < CAP) {
        g_bucket[(size_t)c * CAP + pos] = make_int2(r, __float_as_int(w));
    } else {
        int o = atomicAdd(&g_ovf_cnt, 1);
        if (o < OVF_CAP) g_ovf[o] = e;
    }
}

// ---------------------------------------------------------------------------
// Shared GEMM body: dst = src @ W (+ bias), one thread per row.
// ---------------------------------------------------------------------------
template <bool ADD_BIAS>
__device__ __forceinline__ void gemm_row(const float* __restrict__ src,
                                         const float* sW, const float* sb,
                                         float* __restrict__ dst, int row) {
    float4 acc[D / 4];
#pragma unroll
    for (int j = 0; j < D / 4; j++)
        acc[j] = ADD_BIAS ? ((const float4*)sb)[j]
                          : make_float4(0.f, 0.f, 0.f, 0.f);

    const float4* xr = (const float4*)(src + (size_t)row * D);
#pragma unroll
    for (int k4 = 0; k4 < D / 4; k4++) {
        float4 xv = __ldg(&xr[k4]);
#pragma unroll
        for (int kk = 0; kk < 4; kk++) {
            float xs = (&xv.x)[kk];
            const float4* wr = (const float4*)&sW[(k4 * 4 + kk) * D];
#pragma unroll
            for (int j = 0; j < D / 4; j++) {
                float4 w = wr[j];
                acc[j].x = fmaf(xs, w.x, acc[j].x);
                acc[j].y = fmaf(xs, w.y, acc[j].y);
                acc[j].z = fmaf(xs, w.z, acc[j].z);
                acc[j].w = fmaf(xs, w.w, acc[j].w);
            }
        }
    }
    float4* o = (float4*)(dst + (size_t)row * D);
#pragma unroll
    for (int j = 0; j < D / 4; j++) o[j] = acc[j];
}

// K3 (side stream): out = x @ W0 + b
__global__ void __launch_bounds__(256)
gemmA_kernel(const float* __restrict__ x, const float* __restrict__ W0,
             const float* __restrict__ b, float* __restrict__ out, int N) {
    __shared__ __align__(16) float sW[D * D];
    __shared__ __align__(16) float sb[D];
    for (int i = threadIdx.x; i < D * D; i += blockDim.x) sW[i] = W0[i];
    if (threadIdx.x < D) sb[threadIdx.x] = b[threadIdx.x];
    __syncthreads();
    int row = blockIdx.x * blockDim.x + threadIdx.x;
    if (row < N) gemm_row<true>(x, sW, sb, out, row);
}

// K4 (side stream): g_y = x @ W1
__global__ void __launch_bounds__(256)
gemmY_kernel(const float* __restrict__ x, const float* __restrict__ W1, int N) {
    __shared__ __align__(16) float sW[D * D];
    for (int i = threadIdx.x; i < D * D; i += blockDim.x) sW[i] = W1[i];
    __syncthreads();
    int row = blockIdx.x * blockDim.x + threadIdx.x;
    if (row < N) gemm_row<false>(x, sW, nullptr, g_y, row);
}

// ---------------------------------------------------------------------------
// K5: gather v2. One warp per node; half-warps process alternate edges,
// each lane accumulates a float4 (4 columns). Edge {row, norm} staged in
// shared per 32-edge batch (no SHFL in the inner loop).
//   out[c] += sum_e norm_e * y[r_e]      (y = x @ W1)
// Inline overflow drain for the (statistically impossible) n > CAP case.
// ---------------------------------------------------------------------------
__global__ void __launch_bounds__(256)
gather_kernel(float* __restrict__ out, const void* __restrict__ ei,
              const float* __restrict__ ew, int E) {
    __shared__ int2 sh[8][32];
    int wib  = threadIdx.x >> 5;
    int lane = threadIdx.x & 31;
    int half = lane >> 4;        // 0: even edges, 1: odd edges
    int q    = lane & 15;        // float4 column group
    int node = blockIdx.x * 8 + wib;
    if (node >= N_NODES) return;

    int n_raw = g_cnt[node];
    int n = n_raw < CAP ? n_raw : CAP;
    float dinv_c = dinv_of(g_deg[node]);

    float4 acc = make_float4(0.f, 0.f, 0.f, 0.f);
    const int2* bk = &g_bucket[(size_t)node * CAP];

    for (int base = 0; base < n; base += 32) {
        int m = n - base; if (m > 32) m = 32;
        if (lane < m) {
            int2 ed = bk[base + lane];
            float nm = -dinv_of(g_deg[ed.x]) * __int_as_float(ed.y) * dinv_c;
            sh[wib][lane] = make_int2(ed.x, __float_as_int(nm));
        }
        __syncwarp();
        #pragma unroll 4
        for (int jj = 0; jj < m; jj += 2) {
            int j = jj + half;
            int2 ed = sh[wib][j < m ? j : jj];
            float nm = (j < m) ? __int_as_float(ed.y) : 0.f;
            float4 yv = __ldg((const float4*)(g_y + (size_t)ed.x * D) + q);
            acc.x = fmaf(nm, yv.x, acc.x);
            acc.y = fmaf(nm, yv.y, acc.y);
            acc.z = fmaf(nm, yv.z, acc.z);
            acc.w = fmaf(nm, yv.w, acc.w);
        }
        __syncwarp();
    }

    // Overflow edges for this node (bucket spilled) — statistically dead.
    if (n_raw > CAP) {
        int cnt = g_ovf_cnt; if (cnt > OVF_CAP) cnt = OVF_CAP;
        for (int i = half; i < cnt; i += 2) {
            int e = g_ovf[i];
            int r, c;
            load_edge(ei, E, e, r, c);
            if (c != node) continue;
            float w = __ldg(&ew[e]);
            float nm = -dinv_of(g_deg[r]) * w * dinv_c;
            float4 yv = __ldg((const float4*)(g_y + (size_t)r * D) + q);
            acc.x = fmaf(nm, yv.x, acc.x);
            acc.y = fmaf(nm, yv.y, acc.y);
            acc.z = fmaf(nm, yv.z, acc.z);
            acc.w = fmaf(nm, yv.w, acc.w);
        }
    }

    // Combine halves, then lanes 0-15 RMW the output row.
    acc.x += __shfl_xor_sync(0xffffffffu, acc.x, 16);
    acc.y += __shfl_xor_sync(0xffffffffu, acc.y, 16);
    acc.z += __shfl_xor_sync(0xffffffffu, acc.z, 16);
    acc.w += __shfl_xor_sync(0xffffffffu, acc.w, 16);
    if (half == 0) {
        float4* o = (float4*)(out + (size_t)node * D);
        float4 ov = o[q];
        o[q] = make_float4(ov.x + acc.x, ov.y + acc.y,
                           ov.z + acc.z, ov.w + acc.w);
    }
}

// ---------------------------------------------------------------------------
// Launch: side stream computes out=x@W0+b and y=x@W1 concurrently with the
// zero->edge_pass chain; gather joins, accumulating norm-weighted y rows
// straight into out (overflow handled inline).
// ---------------------------------------------------------------------------
extern "C" void kernel_launch(void* const* d_in, const int* in_sizes, int n_in,
                              void* d_out, int out_size) {
    const float* x  = (const float*)d_in[0];
    const void*  ei = d_in[1];
    const float* ew = (const float*)d_in[2];
    const float* W0 = (const float*)d_in[3];
    const float* W1 = (const float*)d_in[4];
    const float* b  = (const float*)d_in[5];
    float*       out = (float*)d_out;

    int E = in_sizes[2];
    int N = in_sizes[0] / D;

    static cudaStream_t s2 = nullptr;
    static cudaEvent_t evF = nullptr, evJ = nullptr;
    if (s2 == nullptr) {
        cudaStreamCreateWithFlags(&s2, cudaStreamNonBlocking);
        cudaEventCreateWithFlags(&evF, cudaEventDisableTiming);
        cudaEventCreateWithFlags(&evJ, cudaEventDisableTiming);
    }

    // Fork: both GEMMs depend only on x/W0/W1/b
    cudaEventRecord(evF, 0);
    cudaStreamWaitEvent(s2, evF, 0);
    gemmA_kernel<<<(N + 255) / 256, 256, 0, s2>>>(x, W0, b, out, N);
    gemmY_kernel<<<(N + 255) / 256, 256, 0, s2>>>(x, W1, N);
    cudaEventRecord(evJ, s2);

    // Main chain
    zero_detect_kernel<<<(N_NODES + 255) / 256, 256>>>((const int*)ei);
    edge_pass_kernel<<<(E + 255) / 256, 256>>>(ei, ew, E);

    // Join: gather needs out, y, and the buckets
    cudaStreamWaitEvent(0, evJ, 0);
    {
        int blocks = (N_NODES + 7) / 8;
        gather_kernel<<<blocks, 256>>>(out, ei, ew, E);
    }
}

// round 16
// speedup vs baseline: 1.0020x; 1.0020x over previous
#include <cuda_runtime.h>
#include <cstdint>

#define N_NODES 100000
#define D 64
#define CAP 64            // per-node in-edge bucket capacity (Poisson(16), max ~45)
#define OVF_CAP 8192      // overflow edge list (statistically never used)

// Scratch (__device__ globals: allocation-free per harness rules)
__device__ int   g_is64;                          // edge_index dtype flag
__device__ float g_deg[N_NODES];                  // raw weighted out-degree
__device__ int   g_cnt[N_NODES];                  // bucket fill counters
__device__ int2  g_bucket[(size_t)N_NODES * CAP]; // {row, bitcast(w)}
__device__ int   g_ovf_cnt;
__device__ int   g_ovf[OVF_CAP];                  // overflow edge ids
__device__ __align__(16) float g_y[(size_t)N_NODES * D];   // y = x @ W1

__device__ __forceinline__ float dinv_of(float d) {
    return (d > 0.f) ? rsqrtf(d) : 0.f;
}

__device__ __forceinline__ void load_edge(const void* ei, int E, int e,
                                          int& r, int& c) {
    if (g_is64) {
        const long long* p = (const long long*)ei;
        r = (int)p[e];
        c = (int)p[(size_t)E + e];
    } else {
        const int* p = (const int*)ei;
        r = p[e];
        c = p[E + e];
    }
}

// ---------------------------------------------------------------------------
// K1: zero deg + counters; block 0 also detects edge_index dtype.
// ---------------------------------------------------------------------------
__global__ void zero_detect_kernel(const int* __restrict__ ei) {
    int i = blockIdx.x * blockDim.x + threadIdx.x;
    if (i < N_NODES) { g_deg[i] = 0.f; g_cnt[i] = 0; }
    if (i == 0) g_ovf_cnt = 0;
    if (blockIdx.x == 0) {
        __shared__ int any;
        if (threadIdx.x == 0) any = 0;
        __syncthreads();
        int loc = 0;
        for (int k = 1 + 2 * threadIdx.x; k < 4096; k += 2 * blockDim.x)
            loc |= ei[k];
        if (loc) atomicOr(&any, 1);
        __syncthreads();
        if (threadIdx.x == 0) g_is64 = any ? 0 : 1;
    }
}

// ---------------------------------------------------------------------------
// K2: single edge pass — deg[row] += w AND append {row, w} to col's bucket.
// ---------------------------------------------------------------------------
__global__ void edge_pass_kernel(const void* __restrict__ ei,
                                 const float* __restrict__ ew, int E) {
    int e = blockIdx.x * blockDim.x + threadIdx.x;
    if (e >= E) return;
    int r, c;
    load_edge(ei, E, e, r, c);
    float w = __ldg(&ew[e]);
    atomicAdd(&g_deg[r], w);
    int pos = atomicAdd(&g_cnt[c], 1);
    if (pos < CAP) {
        g_bucket[(size_t)c * CAP + pos] = make_int2(r, __float_as_int(w));
    } else {
        int o = atomicAdd(&g_ovf_cnt, 1);
        if (o < OVF_CAP) g_ovf[o] = e;
    }
}

// ---------------------------------------------------------------------------
// Shared GEMM body: dst = src @ W (+ bias), one thread per row.
// ---------------------------------------------------------------------------
template <bool ADD_BIAS>
__device__ __forceinline__ void gemm_row(const float* __restrict__ src,
                                         const float* sW, const float* sb,
                                         float* __restrict__ dst, int row) {
    float4 acc[D / 4];
#pragma unroll
    for (int j = 0; j < D / 4; j++)
        acc[j] = ADD_BIAS ? ((const float4*)sb)[j]
                          : make_float4(0.f, 0.f, 0.f, 0.f);

    const float4* xr = (const float4*)(src + (size_t)row * D);
#pragma unroll
    for (int k4 = 0; k4 < D / 4; k4++) {
        float4 xv = __ldg(&xr[k4]);
#pragma unroll
        for (int kk = 0; kk < 4; kk++) {
            float xs = (&xv.x)[kk];
            const float4* wr = (const float4*)&sW[(k4 * 4 + kk) * D];
#pragma unroll
            for (int j = 0; j < D / 4; j++) {
                float4 w = wr[j];
                acc[j].x = fmaf(xs, w.x, acc[j].x);
                acc[j].y = fmaf(xs, w.y, acc[j].y);
                acc[j].z = fmaf(xs, w.z, acc[j].z);
                acc[j].w = fmaf(xs, w.w, acc[j].w);
            }
        }
    }
    float4* o = (float4*)(dst + (size_t)row * D);
#pragma unroll
    for (int j = 0; j < D / 4; j++) o[j] = acc[j];
}

// K3 (side stream): out = x @ W0 + b
__global__ void __launch_bounds__(256)
gemmA_kernel(const float* __restrict__ x, const float* __restrict__ W0,
             const float* __restrict__ b, float* __restrict__ out, int N) {
    __shared__ __align__(16) float sW[D * D];
    __shared__ __align__(16) float sb[D];
    for (int i = threadIdx.x; i < D * D; i += blockDim.x) sW[i] = W0[i];
    if (threadIdx.x < D) sb[threadIdx.x] = b[threadIdx.x];
    __syncthreads();
    int row = blockIdx.x * blockDim.x + threadIdx.x;
    if (row < N) gemm_row<true>(x, sW, sb, out, row);
}

// K4 (side stream): g_y = x @ W1
__global__ void __launch_bounds__(256)
gemmY_kernel(const float* __restrict__ x, const float* __restrict__ W1, int N) {
    __shared__ __align__(16) float sW[D * D];
    for (int i = threadIdx.x; i < D * D; i += blockDim.x) sW[i] = W1[i];
    __syncthreads();
    int row = blockIdx.x * blockDim.x + threadIdx.x;
    if (row < N) gemm_row<false>(x, sW, nullptr, g_y, row);
}

// ---------------------------------------------------------------------------
// K5: gather v2. One warp per node; half-warps process alternate edges,
// each lane accumulates a float4 (4 columns). Edge {row, norm} staged in
// shared per 32-edge batch (no SHFL in the inner loop).
//   out[c] += sum_e norm_e * y[r_e]      (y = x @ W1)
// Inline overflow drain for the (statistically impossible) n > CAP case.
// ---------------------------------------------------------------------------
__global__ void __launch_bounds__(256)
gather_kernel(float* __restrict__ out, const void* __restrict__ ei,
              const float* __restrict__ ew, int E) {
    __shared__ int2 sh[8][32];
    int wib  = threadIdx.x >> 5;
    int lane = threadIdx.x & 31;
    int half = lane >> 4;        // 0: even edges, 1: odd edges
    int q    = lane & 15;        // float4 column group
    int node = blockIdx.x * 8 + wib;
    if (node >= N_NODES) return;

    int n_raw = g_cnt[node];
    int n = n_raw < CAP ? n_raw : CAP;
    float dinv_c = dinv_of(g_deg[node]);

    float4 acc = make_float4(0.f, 0.f, 0.f, 0.f);
    const int2* bk = &g_bucket[(size_t)node * CAP];

    for (int base = 0; base < n; base += 32) {
        int m = n - base; if (m > 32) m = 32;
        if (lane < m) {
            int2 ed = bk[base + lane];
            float nm = -dinv_of(g_deg[ed.x]) * __int_as_float(ed.y) * dinv_c;
            sh[wib][lane] = make_int2(ed.x, __float_as_int(nm));
        }
        __syncwarp();
        #pragma unroll 4
        for (int jj = 0; jj < m; jj += 2) {
            int j = jj + half;
            int2 ed = sh[wib][j < m ? j : jj];
            float nm = (j < m) ? __int_as_float(ed.y) : 0.f;
            float4 yv = __ldg((const float4*)(g_y + (size_t)ed.x * D) + q);
            acc.x = fmaf(nm, yv.x, acc.x);
            acc.y = fmaf(nm, yv.y, acc.y);
            acc.z = fmaf(nm, yv.z, acc.z);
            acc.w = fmaf(nm, yv.w, acc.w);
        }
        __syncwarp();
    }

    // Overflow edges for this node (bucket spilled) — statistically dead.
    if (n_raw > CAP) {
        int cnt = g_ovf_cnt; if (cnt > OVF_CAP) cnt = OVF_CAP;
        for (int i = half; i < cnt; i += 2) {
            int e = g_ovf[i];
            int r, c;
            load_edge(ei, E, e, r, c);
            if (c != node) continue;
            float w = __ldg(&ew[e]);
            float nm = -dinv_of(g_deg[r]) * w * dinv_c;
            float4 yv = __ldg((const float4*)(g_y + (size_t)r * D) + q);
            acc.x = fmaf(nm, yv.x, acc.x);
            acc.y = fmaf(nm, yv.y, acc.y);
            acc.z = fmaf(nm, yv.z, acc.z);
            acc.w = fmaf(nm, yv.w, acc.w);
        }
    }

    // Combine halves, then lanes 0-15 RMW the output row.
    acc.x += __shfl_xor_sync(0xffffffffu, acc.x, 16);
    acc.y += __shfl_xor_sync(0xffffffffu, acc.y, 16);
    acc.z += __shfl_xor_sync(0xffffffffu, acc.z, 16);
    acc.w += __shfl_xor_sync(0xffffffffu, acc.w, 16);
    if (half == 0) {
        float4* o = (float4*)(out + (size_t)node * D);
        float4 ov = o[q];
        o[q] = make_float4(ov.x + acc.x, ov.y + acc.y,
                           ov.z + acc.z, ov.w + acc.w);
    }
}

// ---------------------------------------------------------------------------
// Launch: side stream computes out=x@W0+b and y=x@W1 concurrently with the
// zero->edge_pass chain; gather joins, accumulating norm-weighted y rows
// straight into out (overflow handled inline).
// ---------------------------------------------------------------------------
extern "C" void kernel_launch(void* const* d_in, const int* in_sizes, int n_in,
                              void* d_out, int out_size) {
    const float* x  = (const float*)d_in[0];
    const void*  ei = d_in[1];
    const float* ew = (const float*)d_in[2];
    const float* W0 = (const float*)d_in[3];
    const float* W1 = (const float*)d_in[4];
    const float* b  = (const float*)d_in[5];
    float*       out = (float*)d_out;

    int E = in_sizes[2];
    int N = in_sizes[0] / D;

    static cudaStream_t s2 = nullptr;
    static cudaEvent_t evF = nullptr, evJ = nullptr;
    if (s2 == nullptr) {
        cudaStreamCreateWithFlags(&s2, cudaStreamNonBlocking);
        cudaEventCreateWithFlags(&evF, cudaEventDisableTiming);
        cudaEventCreateWithFlags(&evJ, cudaEventDisableTiming);
    }

    // Fork: both GEMMs depend only on x/W0/W1/b
    cudaEventRecord(evF, 0);
    cudaStreamWaitEvent(s2, evF, 0);
    gemmA_kernel<<<(N + 255) / 256, 256, 0, s2>>>(x, W0, b, out, N);
    gemmY_kernel<<<(N + 255) / 256, 256, 0, s2>>>(x, W1, N);
    cudaEventRecord(evJ, s2);

    // Main chain
    zero_detect_kernel<<<(N_NODES + 255) / 256, 256>>>((const int*)ei);
    edge_pass_kernel<<<(E + 255) / 256, 256>>>(ei, ew, E);

    // Join: gather needs out, y, and the buckets
    cudaStreamWaitEvent(0, evJ, 0);
    {
        int blocks = (N_NODES + 7) / 8;
        gather_kernel<<<blocks, 256>>>(out, ei, ew, E);
    }
}

// round 17
// speedup vs baseline: 1.0057x; 1.0038x over previous
#include <cuda_runtime.h>
#include <cstdint>

#define N_NODES 100000
#define D 64
#define CAP 64            // per-node in-edge bucket capacity (Poisson(16), max ~45)
#define OVF_CAP 8192      // overflow edge list (statistically never used)

// Scratch (__device__ globals: allocation-free per harness rules)
__device__ int   g_is64;                          // edge_index dtype flag
__device__ float g_deg[N_NODES];                  // raw weighted out-degree
__device__ int   g_cnt[N_NODES];                  // bucket fill counters
__device__ int2  g_bucket[(size_t)N_NODES * CAP]; // {row, bitcast(w)}
__device__ int   g_ovf_cnt;
__device__ int   g_ovf[OVF_CAP];                  // overflow edge ids
__device__ __align__(16) float g_y[(size_t)N_NODES * D];   // y = x @ W1

__device__ __forceinline__ float dinv_of(float d) {
    return (d > 0.f) ? rsqrtf(d) : 0.f;
}

__device__ __forceinline__ void load_edge(const void* ei, int E, int e,
                                          int& r, int& c) {
    if (g_is64) {
        const long long* p = (const long long*)ei;
        r = (int)p[e];
        c = (int)p[(size_t)E + e];
    } else {
        const int* p = (const int*)ei;
        r = p[e];
        c = p[E + e];
    }
}

// ---------------------------------------------------------------------------
// K1: zero deg + counters; block 0 also detects edge_index dtype.
// ---------------------------------------------------------------------------
__global__ void zero_detect_kernel(const int* __restrict__ ei) {
    int i = blockIdx.x * blockDim.x + threadIdx.x;
    if (i < N_NODES) { g_deg[i] = 0.f; g_cnt[i] = 0; }
    if (i == 0) g_ovf_cnt = 0;
    if (blockIdx.x == 0) {
        __shared__ int any;
        if (threadIdx.x == 0) any = 0;
        __syncthreads();
        int loc = 0;
        for (int k = 1 + 2 * threadIdx.x; k < 4096; k += 2 * blockDim.x)
            loc |= ei[k];
        if (loc) atomicOr(&any, 1);
        __syncthreads();
        if (threadIdx.x == 0) g_is64 = any ? 0 : 1;
    }
}

// ---------------------------------------------------------------------------
// K2: single edge pass — deg[row] += w AND append {row, w} to col's bucket.
// ---------------------------------------------------------------------------
__global__ void edge_pass_kernel(const void* __restrict__ ei,
                                 const float* __restrict__ ew, int E) {
    int e = blockIdx.x * blockDim.x + threadIdx.x;
    if (e >= E) return;
    int r, c;
    load_edge(ei, E, e, r, c);
    float w = __ldg(&ew[e]);
    atomicAdd(&g_deg[r], w);
    int pos = atomicAdd(&g_cnt[c], 1);
    if (pos < CAP) {
        g_bucket[(size_t)c * CAP + pos] = make_int2(r, __float_as_int(w));
    } else {
        int o = atomicAdd(&g_ovf_cnt, 1);
        if (o < OVF_CAP) g_ovf[o] = e;
    }
}

// ---------------------------------------------------------------------------
// Shared GEMM body: dst = src @ W (+ bias), one thread per row.
// ---------------------------------------------------------------------------
template <bool ADD_BIAS>
__device__ __forceinline__ void gemm_row(const float* __restrict__ src,
                                         const float* sW, const float* sb,
                                         float* __restrict__ dst, int row) {
    float4 acc[D / 4];
#pragma unroll
    for (int j = 0; j < D / 4; j++)
        acc[j] = ADD_BIAS ? ((const float4*)sb)[j]
                          : make_float4(0.f, 0.f, 0.f, 0.f);

    const float4* xr = (const float4*)(src + (size_t)row * D);
#pragma unroll
    for (int k4 = 0; k4 < D / 4; k4++) {
        float4 xv = __ldg(&xr[k4]);
#pragma unroll
        for (int kk = 0; kk < 4; kk++) {
            float xs = (&xv.x)[kk];
            const float4* wr = (const float4*)&sW[(k4 * 4 + kk) * D];
#pragma unroll
            for (int j = 0; j < D / 4; j++) {
                float4 w = wr[j];
                acc[j].x = fmaf(xs, w.x, acc[j].x);
                acc[j].y = fmaf(xs, w.y, acc[j].y);
                acc[j].z = fmaf(xs, w.z, acc[j].z);
                acc[j].w = fmaf(xs, w.w, acc[j].w);
            }
        }
    }
    float4* o = (float4*)(dst + (size_t)row * D);
#pragma unroll
    for (int j = 0; j < D / 4; j++) o[j] = acc[j];
}

// K3 (side stream): out = x @ W0 + b
__global__ void __launch_bounds__(256)
gemmA_kernel(const float* __restrict__ x, const float* __restrict__ W0,
             const float* __restrict__ b, float* __restrict__ out, int N) {
    __shared__ __align__(16) float sW[D * D];
    __shared__ __align__(16) float sb[D];
    for (int i = threadIdx.x; i < D * D; i += blockDim.x) sW[i] = W0[i];
    if (threadIdx.x < D) sb[threadIdx.x] = b[threadIdx.x];
    __syncthreads();
    int row = blockIdx.x * blockDim.x + threadIdx.x;
    if (row < N) gemm_row<true>(x, sW, sb, out, row);
}

// K4 (side stream): g_y = x @ W1
__global__ void __launch_bounds__(256)
gemmY_kernel(const float* __restrict__ x, const float* __restrict__ W1, int N) {
    __shared__ __align__(16) float sW[D * D];
    for (int i = threadIdx.x; i < D * D; i += blockDim.x) sW[i] = W1[i];
    __syncthreads();
    int row = blockIdx.x * blockDim.x + threadIdx.x;
    if (row < N) gemm_row<false>(x, sW, nullptr, g_y, row);
}

// ---------------------------------------------------------------------------
// K5: gather v2. One warp per node; half-warps process alternate edges,
// each lane accumulates a float4 (4 columns). Edge {row, norm} staged in
// shared per 32-edge batch (no SHFL in the inner loop).
//   out[c] += sum_e norm_e * y[r_e]      (y = x @ W1)
// Inline overflow drain for the (statistically impossible) n > CAP case.
// ---------------------------------------------------------------------------
__global__ void __launch_bounds__(256)
gather_kernel(float* __restrict__ out, const void* __restrict__ ei,
              const float* __restrict__ ew, int E) {
    __shared__ int2 sh[8][32];
    int wib  = threadIdx.x >> 5;
    int lane = threadIdx.x & 31;
    int half = lane >> 4;        // 0: even edges, 1: odd edges
    int q    = lane & 15;        // float4 column group
    int node = blockIdx.x * 8 + wib;
    if (node >= N_NODES) return;

    int n_raw = g_cnt[node];
    int n = n_raw < CAP ? n_raw : CAP;
    float dinv_c = dinv_of(g_deg[node]);

    float4 acc = make_float4(0.f, 0.f, 0.f, 0.f);
    const int2* bk = &g_bucket[(size_t)node * CAP];

    for (int base = 0; base < n; base += 32) {
        int m = n - base; if (m > 32) m = 32;
        if (lane < m) {
            int2 ed = bk[base + lane];
            float nm = -dinv_of(g_deg[ed.x]) * __int_as_float(ed.y) * dinv_c;
            sh[wib][lane] = make_int2(ed.x, __float_as_int(nm));
        }
        __syncwarp();
        #pragma unroll 4
        for (int jj = 0; jj < m; jj += 2) {
            int j = jj + half;
            int2 ed = sh[wib][j < m ? j : jj];
            float nm = (j < m) ? __int_as_float(ed.y) : 0.f;
            float4 yv = __ldg((const float4*)(g_y + (size_t)ed.x * D) + q);
            acc.x = fmaf(nm, yv.x, acc.x);
            acc.y = fmaf(nm, yv.y, acc.y);
            acc.z = fmaf(nm, yv.z, acc.z);
            acc.w = fmaf(nm, yv.w, acc.w);
        }
        __syncwarp();
    }

    // Overflow edges for this node (bucket spilled) — statistically dead.
    if (n_raw > CAP) {
        int cnt = g_ovf_cnt; if (cnt > OVF_CAP) cnt = OVF_CAP;
        for (int i = half; i < cnt; i += 2) {
            int e = g_ovf[i];
            int r, c;
            load_edge(ei, E, e, r, c);
            if (c != node) continue;
            float w = __ldg(&ew[e]);
            float nm = -dinv_of(g_deg[r]) * w * dinv_c;
            float4 yv = __ldg((const float4*)(g_y + (size_t)r * D) + q);
            acc.x = fmaf(nm, yv.x, acc.x);
            acc.y = fmaf(nm, yv.y, acc.y);
            acc.z = fmaf(nm, yv.z, acc.z);
            acc.w = fmaf(nm, yv.w, acc.w);
        }
    }

    // Combine halves, then lanes 0-15 RMW the output row.
    acc.x += __shfl_xor_sync(0xffffffffu, acc.x, 16);
    acc.y += __shfl_xor_sync(0xffffffffu, acc.y, 16);
    acc.z += __shfl_xor_sync(0xffffffffu, acc.z, 16);
    acc.w += __shfl_xor_sync(0xffffffffu, acc.w, 16);
    if (half == 0) {
        float4* o = (float4*)(out + (size_t)node * D);
        float4 ov = o[q];
        o[q] = make_float4(ov.x + acc.x, ov.y + acc.y,
                           ov.z + acc.z, ov.w + acc.w);
    }
}

// ---------------------------------------------------------------------------
// Launch: side stream computes out=x@W0+b and y=x@W1 concurrently with the
// zero->edge_pass chain; gather joins, accumulating norm-weighted y rows
// straight into out (overflow handled inline).
// ---------------------------------------------------------------------------
extern "C" void kernel_launch(void* const* d_in, const int* in_sizes, int n_in,
                              void* d_out, int out_size) {
    const float* x  = (const float*)d_in[0];
    const void*  ei = d_in[1];
    const float* ew = (const float*)d_in[2];
    const float* W0 = (const float*)d_in[3];
    const float* W1 = (const float*)d_in[4];
    const float* b  = (const float*)d_in[5];
    float*       out = (float*)d_out;

    int E = in_sizes[2];
    int N = in_sizes[0] / D;

    static cudaStream_t s2 = nullptr;
    static cudaEvent_t evF = nullptr, evJ = nullptr;
    if (s2 == nullptr) {
        cudaStreamCreateWithFlags(&s2, cudaStreamNonBlocking);
        cudaEventCreateWithFlags(&evF, cudaEventDisableTiming);
        cudaEventCreateWithFlags(&evJ, cudaEventDisableTiming);
    }

    // Fork: both GEMMs depend only on x/W0/W1/b
    cudaEventRecord(evF, 0);
    cudaStreamWaitEvent(s2, evF, 0);
    gemmA_kernel<<<(N + 255) / 256, 256, 0, s2>>>(x, W0, b, out, N);
    gemmY_kernel<<<(N + 255) / 256, 256, 0, s2>>>(x, W1, N);
    cudaEventRecord(evJ, s2);

    // Main chain
    zero_detect_kernel<<<(N_NODES + 255) / 256, 256>>>((const int*)ei);
    edge_pass_kernel<<<(E + 255) / 256, 256>>>(ei, ew, E);

    // Join: gather needs out, y, and the buckets
    cudaStreamWaitEvent(0, evJ, 0);
    {
        int blocks = (N_NODES + 7) / 8;
        gather_kernel<<<blocks, 256>>>(out, ei, ew, E);
    }
}